// round 9
// baseline (speedup 1.0000x reference)
#include <cuda_runtime.h>
#include <math.h>

// ---------------- problem constants ----------------
#define B_ 256
#define T_ 512
#define M_ 16
#define C_ 16
#define H_ 768
#define BT_  (B_ * T_)           // 131072
#define BTM_ (BT_ * M_)          // 2097152
#define BH_  (B_ * H_)           // 196608

// ---------------- GRU partition ----------------
#define GT_   288                // threads per GRU CTA (9 warps)
#define SROWS 36                 // 3 gates x 12 hidden units
#define HSL   12                 // hidden units per CTA
#define BTILE 128                // batches per CTA
#define ST_P  129                // padded batch stride in smem

// ---------------- scratch (static device memory; no allocs) ----------------
__device__ float g_Z[BTM_];
__device__ float g_hill[BTM_];
__device__ float g_xin[BTM_];
__device__ float g_hseq[100859904];   // (T_+1) * B_ * H_ = 513*256*768

// ---------------- helpers ----------------
__device__ __forceinline__ float sigmoidf_(float x) { return 1.0f / (1.0f + expf(-x)); }
__device__ __forceinline__ float softplusf_(float x) {
    return fmaxf(x, 0.0f) + log1pf(expf(-fabsf(x)));
}
__device__ __forceinline__ float wredux(float v) {
#pragma unroll
    for (int off = 16; off; off >>= 1) v += __shfl_xor_sync(0xffffffffu, v, off);
    return v;
}

// =====================================================================
// kernel 1: causal encoder -> g_Z   (one thread per (b,t))
// =====================================================================
__global__ void __launch_bounds__(256)
enc_kernel(const float* __restrict__ Xm, const float* __restrict__ A,
           const float* __restrict__ ew1, const float* __restrict__ eb1,
           const float* __restrict__ ew2, const float* __restrict__ eb2,
           const float* __restrict__ nw, const float* __restrict__ nb) {
    __shared__ float sA[256], sw1[512], sw2[256], snw[512];
    __shared__ float sb1[16], sb2[16], snb[16];
    int tid = threadIdx.x;
    sA[tid] = A[tid];
    sw2[tid] = ew2[tid];
    sw1[tid] = ew1[tid];       sw1[tid + 256] = ew1[tid + 256];
    snw[tid] = nw[tid];        snw[tid + 256] = nw[tid + 256];
    if (tid < 16) { sb1[tid] = eb1[tid]; sb2[tid] = eb2[tid]; snb[tid] = nb[tid]; }
    __syncthreads();

    int idx = blockIdx.x * 256 + tid;      // b*T + t, grid covers exactly B*T
    float x[16];
#pragma unroll
    for (int j = 0; j < 16; j++) x[j] = Xm[(size_t)idx * 16 + j];

    float send[16], recv[16];
#pragma unroll
    for (int i = 0; i < 16; i++) {
        float s = 0.f, r = 0.f;
#pragma unroll
        for (int j = 0; j < 16; j++) { s += x[j] * sA[i * 16 + j]; r += x[j] * sA[j * 16 + i]; }
        send[i] = s; recv[i] = r;
    }
    float h1[16];
#pragma unroll
    for (int i = 0; i < 16; i++) {
        float s = sb1[i];
#pragma unroll
        for (int j = 0; j < 16; j++)
            s += send[j] * sw1[i * 32 + j] + recv[j] * sw1[i * 32 + 16 + j];
        h1[i] = fmaxf(s, 0.f);
    }
    float h2[16];
#pragma unroll
    for (int i = 0; i < 16; i++) {
        float s = sb2[i];
#pragma unroll
        for (int j = 0; j < 16; j++) s += h1[j] * sw2[i * 16 + j];
        h2[i] = fmaxf(s, 0.f);
    }
#pragma unroll
    for (int i = 0; i < 16; i++) {
        float s = snb[i];
#pragma unroll
        for (int j = 0; j < 16; j++)
            s += x[j] * snw[i * 32 + j] + h2[j] * snw[i * 32 + 16 + j];
        g_Z[(size_t)idx * 16 + i] = fmaxf(s, 0.f);
    }
}

// =====================================================================
// kernel 2: adstock + hill; g_xin = hill + Z   (one thread per (b,m))
// =====================================================================
__global__ void __launch_bounds__(256)
adstock_kernel(const float* __restrict__ Xm, const float* __restrict__ alpha,
               const float* __restrict__ hill_a, const float* __restrict__ hill_g) {
    int tid = blockIdx.x * blockDim.x + threadIdx.x;   // < B*M = 4096
    int b = tid >> 4, m = tid & 15;
    float a  = fminf(fmaxf(alpha[m], 0.0f), 1.0f);
    float ha = fminf(fmaxf(hill_a[m], 0.1f), 3.0f);
    float hg = fminf(fmaxf(hill_g[m], 0.1f), 2.0f);
    float hga = powf(hg, ha);

    const float* xm = Xm + (size_t)b * T_ * M_ + m;
    float* hil = g_hill + (size_t)b * T_ * M_ + m;
    float* xin = g_xin + (size_t)b * T_ * M_ + m;
    const float* zp = g_Z + (size_t)b * T_ * M_ + m;

    float prev = 0.f, cmax = -1e30f;
    for (int t = 0; t < T_; t++) {
        float cur = xm[t * M_] + a * prev;   // t=0: x + a*0 = x  (matches ref)
        prev = cur;
        hil[t * M_] = cur;                   // temp: adstock value
        cmax = fmaxf(cmax, cur);
    }
    cmax = fmaxf(cmax, 1e-6f);
    float inv = 1.0f / cmax;
    for (int t = 0; t < T_; t++) {
        float xn = fmaxf(hil[t * M_] * inv, 0.0f);
        float num = powf(xn, ha);
        float h = num / (num + hga + 1e-8f);
        hil[t * M_] = h;
        xin[t * M_] = h + zp[t * M_];
    }
}

// =====================================================================
// kernel 3: h0 broadcast into slot 0 of g_hseq
// =====================================================================
__global__ void __launch_bounds__(256)
hinit_kernel(const float* __restrict__ h0) {
    int idx = blockIdx.x * 256 + threadIdx.x;     // < B*H
    int j = idx % H_;
    g_hseq[idx] = h0[j];
}

// =====================================================================
// kernel 4: one GRU timestep. 128 CTAs = 2 batch-tiles x 64 hidden-slices.
// slot t of g_hseq = h_{t-1} (slot 0 = h_init); writes slot t+1.
// =====================================================================
extern __shared__ float g_sm[];

__global__ void __launch_bounds__(GT_, 1)
gru_step_kernel(int t, const float* __restrict__ Xc,
                const float* __restrict__ W_ih, const float* __restrict__ W_hh,
                const float* __restrict__ b_ih, const float* __restrict__ b_hh) {
    float* Ws = g_sm;              // [36][768]          27648
    float* Wi = Ws + 27648;        // [36][32]            1152
    float* bi = Wi + 1152;         // [40]
    float* bh = bi + 40;           // [40]
    float* xs = bh + 40;           // [32][129]           4128
    float* st = xs + 4128;         // [64][129] = 8256 ; reused as gbuf [48][129]

    const int tid = threadIdx.x;
    const int tx = tid & 31, ty = tid >> 5;     // ty 0..8
    const int bt = blockIdx.x >> 6;             // 0..1
    const int hs = blockIdx.x & 63;             // 0..63
    const int j0 = hs * HSL;
    const int b0 = bt * BTILE;

    const float* hp = g_hseq + (size_t)t * BH_;
    float* ho = g_hseq + (size_t)(t + 1) * BH_;

    // ---- load weight slices ----
    for (int e = tid; e < SROWS * 768; e += GT_) {
        int r = e / 768, k = e - r * 768;
        int grow = (r < 12) ? (j0 + r) : (r < 24) ? (H_ + j0 + r - 12) : (2 * H_ + j0 + r - 24);
        Ws[e] = W_hh[(size_t)grow * H_ + k];
    }
    for (int e = tid; e < SROWS * 32; e += GT_) {
        int r = e >> 5, c = e & 31;
        int grow = (r < 12) ? (j0 + r) : (r < 24) ? (H_ + j0 + r - 12) : (2 * H_ + j0 + r - 24);
        Wi[e] = W_ih[grow * 32 + c];
    }
    if (tid < SROWS) {
        int r = tid;
        int grow = (r < 12) ? (j0 + r) : (r < 24) ? (H_ + j0 + r - 12) : (2 * H_ + j0 + r - 24);
        bi[r] = b_ih[grow]; bh[r] = b_hh[grow];
    }
    // ---- stage x = concat(hill+Z, Xc) : xs[c][b] ----
    for (int e = tid; e < 32 * BTILE; e += GT_) {
        int c = e >> 7, b = e & 127;
        float v;
        if (c < 16) v = g_xin[((size_t)(b0 + b) * T_ + t) * M_ + c];
        else        v = Xc[((size_t)(b0 + b) * T_ + t) * C_ + (c - 16)];
        xs[c * ST_P + b] = v;
    }

    float acc[4][4];
#pragma unroll
    for (int i = 0; i < 4; i++)
#pragma unroll
        for (int j = 0; j < 4; j++) acc[i][j] = 0.f;

    const int r0 = ty * 4;   // this thread's 4 gate rows (all within one gate group)

    for (int kc = 0; kc < 12; kc++) {
        __syncthreads();   // also makes Ws/Wi/xs visible before first compute
        for (int e = tid; e < 64 * BTILE; e += GT_) {
            int b = e >> 6, kk = e & 63;
            st[kk * ST_P + b] = hp[(size_t)(b0 + b) * H_ + kc * 64 + kk];
        }
        __syncthreads();
        const float* wsp = Ws + r0 * 768 + kc * 64;
#pragma unroll 4
        for (int kk = 0; kk < 64; kk++) {
            float w0 = wsp[kk];
            float w1 = wsp[768 + kk];
            float w2 = wsp[1536 + kk];
            float w3 = wsp[2304 + kk];
            const float* sp = st + kk * ST_P + tx;
            float h0v = sp[0], h1v = sp[32], h2v = sp[64], h3v = sp[96];
            acc[0][0] += w0 * h0v; acc[0][1] += w0 * h1v; acc[0][2] += w0 * h2v; acc[0][3] += w0 * h3v;
            acc[1][0] += w1 * h0v; acc[1][1] += w1 * h1v; acc[1][2] += w1 * h2v; acc[1][3] += w1 * h3v;
            acc[2][0] += w2 * h0v; acc[2][1] += w2 * h1v; acc[2][2] += w2 * h2v; acc[2][3] += w2 * h3v;
            acc[3][0] += w3 * h0v; acc[3][1] += w3 * h1v; acc[3][2] += w3 * h2v; acc[3][3] += w3 * h3v;
        }
    }

    // ---- input-part (kept separate for the n gate) ----
    float ax[4][4];
#pragma unroll
    for (int i = 0; i < 4; i++)
#pragma unroll
        for (int j = 0; j < 4; j++) ax[i][j] = 0.f;
#pragma unroll
    for (int c = 0; c < 32; c++) {
        float w0 = Wi[(r0 + 0) * 32 + c];
        float w1 = Wi[(r0 + 1) * 32 + c];
        float w2 = Wi[(r0 + 2) * 32 + c];
        float w3 = Wi[(r0 + 3) * 32 + c];
        const float* xp = xs + c * ST_P + tx;
        float x0 = xp[0], x1 = xp[32], x2 = xp[64], x3 = xp[96];
        ax[0][0] += w0 * x0; ax[0][1] += w0 * x1; ax[0][2] += w0 * x2; ax[0][3] += w0 * x3;
        ax[1][0] += w1 * x0; ax[1][1] += w1 * x1; ax[1][2] += w1 * x2; ax[1][3] += w1 * x3;
        ax[2][0] += w2 * x0; ax[2][1] += w2 * x1; ax[2][2] += w2 * x2; ax[2][3] += w2 * x3;
        ax[3][0] += w3 * x0; ax[3][1] += w3 * x1; ax[3][2] += w3 * x2; ax[3][3] += w3 * x3;
    }

    __syncthreads();     // everyone done reading st -> reuse as gate buffer
    float* gb = st;      // rows 0..11: r (combined), 12..23: z (combined),
                         // 24..35: n hidden-part(+bh), 36..47: n input-part(+bi)
#pragma unroll
    for (int rr = 0; rr < 4; rr++) {
        int rl = r0 + rr;
#pragma unroll
        for (int bb = 0; bb < 4; bb++) {
            int b = tx + 32 * bb;
            if (rl < 24) {
                gb[rl * ST_P + b] = acc[rr][bb] + ax[rr][bb] + bi[rl] + bh[rl];
            } else {
                gb[rl * ST_P + b]        = acc[rr][bb] + bh[rl];     // hn
                gb[(rl + 12) * ST_P + b] = ax[rr][bb] + bi[rl];      // inn
            }
        }
    }
    __syncthreads();

    // ---- gate nonlinearity + state update ----
    for (int e = tid; e < HSL * BTILE; e += GT_) {
        int b = e / HSL, j = e - b * HSL;
        float rg  = sigmoidf_(gb[j * ST_P + b]);
        float zg  = sigmoidf_(gb[(12 + j) * ST_P + b]);
        float hn  = gb[(24 + j) * ST_P + b];
        float inn = gb[(36 + j) * ST_P + b];
        float n   = tanhf(inn + rg * hn);
        float hv  = hp[(size_t)(b0 + b) * H_ + j0 + j];
        ho[(size_t)(b0 + b) * H_ + j0 + j] = (1.f - zg) * n + zg * hv;
    }
}

// =====================================================================
// kernel 5: heads. One warp handles 8 consecutive (b,t) items.
// grid 2048 x 256 threads (8 warps x 8 items = 64 items/CTA).
// =====================================================================
__global__ void __launch_bounds__(256, 1)
heads_kernel(const float* __restrict__ Xc,
             const float* __restrict__ wraw_w, const float* __restrict__ wraw_b,
             const float* __restrict__ ctrl_w, const float* __restrict__ ctrl_b,
             const float* __restrict__ reg_emb, const float* __restrict__ bias,
             float* __restrict__ out_y, float* __restrict__ out_w, float* __restrict__ out_c) {
    extern __shared__ float hsm[];
    float* sww = hsm;              // 16*768
    float* scw = sww + 12288;      // 768*16
    float* scb = scw + 12288;      // 768
    float* srg = scb + 768;        // 768
    float* swb = srg + 768;        // 16
    int tid = threadIdx.x;
    for (int e = tid; e < 12288; e += 256) { sww[e] = wraw_w[e]; scw[e] = ctrl_w[e]; }
    for (int e = tid; e < 768; e += 256) { scb[e] = ctrl_b[e]; srg[e] = reg_emb[e]; }
    if (tid < 16) swb[tid] = wraw_b[tid];
    __syncthreads();

    int wid = tid >> 5, lane = tid & 31;
    float bias0 = bias[0];

    // reg term (constant): 0.3 * sum(reg_emb[0])
    float rp = 0.f;
#pragma unroll
    for (int i = 0; i < 24; i++) rp += srg[lane + 32 * i];
    rp = wredux(rp) * 0.3f;

    for (int it = 0; it < 8; it++) {
        int n = blockIdx.x * 64 + wid * 8 + it;   // < 131072
        int b = n >> 9, t = n & 511;

        // ---- w_pos = softplus(h . wraw_w^T + b) ----
        const float* hrow = g_hseq + (size_t)(t + 1) * BH_ + (size_t)b * H_;
        float hv[24];
#pragma unroll
        for (int i = 0; i < 24; i++) hv[i] = hrow[lane + 32 * i];
        float wp[16];
#pragma unroll
        for (int m = 0; m < 16; m++) {
            float p = 0.f;
#pragma unroll
            for (int i = 0; i < 24; i++) p += hv[i] * sww[m * 768 + lane + 32 * i];
            p = wredux(p);
            wp[m] = softplusf_(p + swb[m]);
        }
        if (t == 0) {
            // blend with raw w_pos at t=1: w0 = 0.5*wp(t=1) + 0.5*wp(t=0)
            const float* h2 = g_hseq + (size_t)2 * BH_ + (size_t)b * H_;
            float h2v[24];
#pragma unroll
            for (int i = 0; i < 24; i++) h2v[i] = h2[lane + 32 * i];
#pragma unroll
            for (int m = 0; m < 16; m++) {
                float p = 0.f;
#pragma unroll
                for (int i = 0; i < 24; i++) p += h2v[i] * sww[m * 768 + lane + 32 * i];
                p = wredux(p);
                wp[m] = 0.5f * softplusf_(p + swb[m]) + 0.5f * wp[m];
            }
        }

        // ---- contrib + media ----
        float media = 0.f;
        const float* hillrow = g_hill + ((size_t)b * T_ + t) * M_;
        float cb[16];
#pragma unroll
        for (int m = 0; m < 16; m++) { cb[m] = hillrow[m] * wp[m]; media += cb[m]; }

        // ---- ctrl term ----
        float xc[16];
#pragma unroll
        for (int c = 0; c < 16; c++) xc[c] = Xc[((size_t)b * T_ + t) * C_ + c];
        float ct = 0.f;
#pragma unroll
        for (int i = 0; i < 24; i++) {
            int j = lane + 32 * i;
            float s = scb[j];
#pragma unroll
            for (int c = 0; c < 16; c++) s += xc[c] * scw[j * 16 + c];
            ct += fmaxf(s, 0.f);
        }
        ct = wredux(ct) * 0.3f;

        float y = media + ct + rp + bias0;
        if (lane == 0) out_y[(size_t)b * T_ + t] = y;
        if (out_w && lane < 16) out_w[((size_t)b * T_ + t) * M_ + lane] = wp[lane];
        if (out_c && lane < 16) out_c[((size_t)b * T_ + t) * M_ + lane] = cb[lane];
    }
}

// =====================================================================
// launch
// =====================================================================
extern "C" void kernel_launch(void* const* d_in, const int* in_sizes, int n_in,
                              void* d_out, int out_size) {
    const float* Xm     = (const float*)d_in[0];
    const float* Xc     = (const float*)d_in[1];
    /* d_in[2] = R (int32) unused in forward */
    const float* A      = (const float*)d_in[3];
    const float* ew1    = (const float*)d_in[4];
    const float* eb1    = (const float*)d_in[5];
    const float* ew2    = (const float*)d_in[6];
    const float* eb2    = (const float*)d_in[7];
    const float* nw     = (const float*)d_in[8];
    const float* nb     = (const float*)d_in[9];
    const float* W_ih   = (const float*)d_in[10];
    const float* W_hh   = (const float*)d_in[11];
    const float* b_ih   = (const float*)d_in[12];
    const float* b_hh   = (const float*)d_in[13];
    const float* wraw_w = (const float*)d_in[14];
    const float* wraw_b = (const float*)d_in[15];
    const float* alpha  = (const float*)d_in[16];
    const float* hill_a = (const float*)d_in[17];
    const float* hill_g = (const float*)d_in[18];
    const float* ctrl_w = (const float*)d_in[19];
    const float* ctrl_b = (const float*)d_in[20];
    const float* regemb = (const float*)d_in[21];
    const float* bias   = (const float*)d_in[22];
    const float* h0     = (const float*)d_in[23];

    const int GRU_SMEM  = (27648 + 1152 + 40 + 40 + 4128 + 8256) * 4;   // 165056
    const int HEAD_SMEM = (12288 + 12288 + 768 + 768 + 16) * 4;         // 104512
    cudaFuncSetAttribute(gru_step_kernel, cudaFuncAttributeMaxDynamicSharedMemorySize, GRU_SMEM);
    cudaFuncSetAttribute(heads_kernel, cudaFuncAttributeMaxDynamicSharedMemorySize, HEAD_SMEM);

    enc_kernel<<<BT_ / 256, 256>>>(Xm, A, ew1, eb1, ew2, eb2, nw, nb);
    adstock_kernel<<<(B_ * M_) / 256, 256>>>(Xm, alpha, hill_a, hill_g);
    hinit_kernel<<<BH_ / 256, 256>>>(h0);

    for (int t = 0; t < T_; t++)
        gru_step_kernel<<<128, GT_, GRU_SMEM>>>(t, Xc, W_ih, W_hh, b_ih, b_hh);

    float* out = (float*)d_out;
    float* oy = out;
    float* ow = nullptr;
    float* oc = nullptr;
    if (out_size >= BT_ + 2 * BTM_) { ow = out + BT_; oc = out + BT_ + BTM_; }
    else if (out_size >= BT_ + BTM_) { ow = out + BT_; }

    heads_kernel<<<BT_ / 64, 256, HEAD_SMEM>>>(Xc, wraw_w, wraw_b, ctrl_w, ctrl_b,
                                               regemb, bias, oy, ow, oc);
}

// round 10
// speedup vs baseline: 1.9541x; 1.9541x over previous
#include <cuda_runtime.h>
#include <math.h>

// ---------------- problem constants ----------------
#define B_ 256
#define T_ 512
#define M_ 16
#define C_ 16
#define H_ 768
#define BT_  (B_ * T_)           // 131072
#define BTM_ (BT_ * M_)          // 2097152
#define BH_  (B_ * H_)           // 196608

// ---------------- GRU partition ----------------
#define GT_   288                // threads per GRU CTA (9 warps)
#define SROWS 36                 // 3 gates x 12 hidden units
#define HSL   12                 // hidden units per CTA
#define STP   130                // padded batch stride (even -> LDS.64 aligned)

// ---------------- scratch (static device memory; no allocs) ----------------
__device__ float g_Z[BTM_];
__device__ float g_hill[BTM_];
__device__ float g_xin[BTM_];
__device__ float g_hseq[100859904];   // (T_+1) * B_ * H_ = 513*256*768
__device__ unsigned g_arrive;
__device__ unsigned g_release;

// ---------------- helpers ----------------
__device__ __forceinline__ float sigmoidf_(float x) { return 1.0f / (1.0f + expf(-x)); }
__device__ __forceinline__ float softplusf_(float x) {
    return fmaxf(x, 0.0f) + log1pf(expf(-fabsf(x)));
}
__device__ __forceinline__ float wredux(float v) {
#pragma unroll
    for (int off = 16; off; off >>= 1) v += __shfl_xor_sync(0xffffffffu, v, off);
    return v;
}

// packed fp32x2 ops (Blackwell FFMA2 — PTX only)
#define FMA2(acc, a, b) asm("fma.rn.f32x2 %0, %1, %2, %3;" : "=l"(acc) : "l"(a), "l"(b), "l"(acc))
#define PACK2(d, s)     asm("mov.b64 %0, {%1, %1};" : "=l"(d) : "r"(s))
#define UNPK2(lo, hi, v) asm("mov.b64 {%0, %1}, %2;" : "=f"(lo), "=f"(hi) : "l"(v))

// =====================================================================
// kernel 1: causal encoder -> g_Z   (one thread per (b,t))
// =====================================================================
__global__ void __launch_bounds__(256)
enc_kernel(const float* __restrict__ Xm, const float* __restrict__ A,
           const float* __restrict__ ew1, const float* __restrict__ eb1,
           const float* __restrict__ ew2, const float* __restrict__ eb2,
           const float* __restrict__ nw, const float* __restrict__ nb) {
    __shared__ float sA[256], sw1[512], sw2[256], snw[512];
    __shared__ float sb1[16], sb2[16], snb[16];
    int tid = threadIdx.x;
    sA[tid] = A[tid];
    sw2[tid] = ew2[tid];
    sw1[tid] = ew1[tid];       sw1[tid + 256] = ew1[tid + 256];
    snw[tid] = nw[tid];        snw[tid + 256] = nw[tid + 256];
    if (tid < 16) { sb1[tid] = eb1[tid]; sb2[tid] = eb2[tid]; snb[tid] = nb[tid]; }
    __syncthreads();

    int idx = blockIdx.x * 256 + tid;      // b*T + t
    float x[16];
#pragma unroll
    for (int j = 0; j < 16; j++) x[j] = Xm[(size_t)idx * 16 + j];

    float send[16], recv[16];
#pragma unroll
    for (int i = 0; i < 16; i++) {
        float s = 0.f, r = 0.f;
#pragma unroll
        for (int j = 0; j < 16; j++) { s += x[j] * sA[i * 16 + j]; r += x[j] * sA[j * 16 + i]; }
        send[i] = s; recv[i] = r;
    }
    float h1[16];
#pragma unroll
    for (int i = 0; i < 16; i++) {
        float s = sb1[i];
#pragma unroll
        for (int j = 0; j < 16; j++)
            s += send[j] * sw1[i * 32 + j] + recv[j] * sw1[i * 32 + 16 + j];
        h1[i] = fmaxf(s, 0.f);
    }
    float h2[16];
#pragma unroll
    for (int i = 0; i < 16; i++) {
        float s = sb2[i];
#pragma unroll
        for (int j = 0; j < 16; j++) s += h1[j] * sw2[i * 16 + j];
        h2[i] = fmaxf(s, 0.f);
    }
#pragma unroll
    for (int i = 0; i < 16; i++) {
        float s = snb[i];
#pragma unroll
        for (int j = 0; j < 16; j++)
            s += x[j] * snw[i * 32 + j] + h2[j] * snw[i * 32 + 16 + j];
        g_Z[(size_t)idx * 16 + i] = fmaxf(s, 0.f);
    }
}

// =====================================================================
// kernel 2: adstock + hill; g_xin = hill + Z   (one thread per (b,m))
// =====================================================================
__global__ void __launch_bounds__(256)
adstock_kernel(const float* __restrict__ Xm, const float* __restrict__ alpha,
               const float* __restrict__ hill_a, const float* __restrict__ hill_g) {
    int tid = blockIdx.x * blockDim.x + threadIdx.x;   // < B*M
    int b = tid >> 4, m = tid & 15;
    float a  = fminf(fmaxf(alpha[m], 0.0f), 1.0f);
    float ha = fminf(fmaxf(hill_a[m], 0.1f), 3.0f);
    float hg = fminf(fmaxf(hill_g[m], 0.1f), 2.0f);
    float hga = powf(hg, ha);

    const float* xm = Xm + (size_t)b * T_ * M_ + m;
    float* hil = g_hill + (size_t)b * T_ * M_ + m;
    float* xin = g_xin + (size_t)b * T_ * M_ + m;
    const float* zp = g_Z + (size_t)b * T_ * M_ + m;

    float prev = 0.f, cmax = -1e30f;
    for (int t = 0; t < T_; t++) {
        float cur = xm[t * M_] + a * prev;
        prev = cur;
        hil[t * M_] = cur;
        cmax = fmaxf(cmax, cur);
    }
    cmax = fmaxf(cmax, 1e-6f);
    float inv = 1.0f / cmax;
    for (int t = 0; t < T_; t++) {
        float xn = fmaxf(hil[t * M_] * inv, 0.0f);
        float num = powf(xn, ha);
        float h = num / (num + hga + 1e-8f);
        hil[t * M_] = h;
        xin[t * M_] = h + zp[t * M_];
    }
}

// =====================================================================
// kernel 3: h0 broadcast into slot 0 of g_hseq + barrier reset
// =====================================================================
__global__ void __launch_bounds__(256)
hinit_kernel(const float* __restrict__ h0) {
    int idx = blockIdx.x * 256 + threadIdx.x;     // < B*H
    if (idx == 0) { g_arrive = 0u; g_release = 0u; }
    int j = idx % H_;
    g_hseq[idx] = h0[j];
}

// =====================================================================
// kernel 4: persistent GRU — all 512 steps in one kernel.
// 128 CTAs = 2 batch-tiles x 64 hidden-slices; weights resident in smem;
// double-buffered h staging; packed f32x2 FMA; grid barrier per step.
// Thread (tx,ty): gate rows r0..r0+3 (r0=4*ty), batches {2tx,2tx+1,64+2tx,64+2tx+1}.
// =====================================================================
extern __shared__ float g_sm[];

__global__ void __launch_bounds__(GT_, 1)
gru_persist_kernel(const float* __restrict__ Xc,
                   const float* __restrict__ W_ih, const float* __restrict__ W_hh,
                   const float* __restrict__ b_ih, const float* __restrict__ b_hh) {
    float* Ws   = g_sm;              // [36][768]        27648
    float* Wi   = Ws + 27648;        // [36][32]          1152
    float* bi   = Wi + 1152;         // [40]
    float* bh   = bi + 40;           // [40]
    float* xs   = bh + 40;           // [32][130]         4160
    float* buf0 = xs + 4160;         // [64][130]         8320
    float* buf1 = buf0 + 8320;       // [64][130]         8320
    // total 49680 floats = 198720 B

    const int tid = threadIdx.x;
    const int tx = tid & 31, ty = tid >> 5;     // ty 0..8
    const int bt = blockIdx.x >> 6;             // 0..1
    const int hs = blockIdx.x & 63;             // 0..63
    const int j0 = hs * HSL;
    const int b0 = bt * 128;
    const int r0 = ty * 4;

    // ---- load weight slices ONCE ----
    for (int e = tid; e < SROWS * 768; e += GT_) {
        int r = e / 768, k = e - r * 768;
        int grow = (r < 12) ? (j0 + r) : (r < 24) ? (H_ + j0 + r - 12) : (2 * H_ + j0 + r - 24);
        Ws[e] = W_hh[(size_t)grow * H_ + k];
    }
    for (int e = tid; e < SROWS * 32; e += GT_) {
        int r = e >> 5, c = e & 31;
        int grow = (r < 12) ? (j0 + r) : (r < 24) ? (H_ + j0 + r - 12) : (2 * H_ + j0 + r - 24);
        Wi[e] = W_ih[grow * 32 + c];
    }
    if (tid < SROWS) {
        int r = tid;
        int grow = (r < 12) ? (j0 + r) : (r < 24) ? (H_ + j0 + r - 12) : (2 * H_ + j0 + r - 24);
        bi[r] = b_ih[grow]; bh[r] = b_hh[grow];
    }

    const int skk = tid & 63;   // staging column (k within chunk)
    const int sb  = tid >> 6;   // staging batch base (0..3), valid for tid<256

    for (int t = 0; t < T_; t++) {
        const float* hp = g_hseq + (size_t)t * BH_;
        float* ho = g_hseq + (size_t)(t + 1) * BH_;

        // ---- stage x = concat(hill+Z, Xc) : xs[c][b] ----
        for (int e = tid; e < 32 * 128; e += GT_) {
            int c = e >> 7, b = e & 127;
            float v = (c < 16) ? g_xin[((size_t)(b0 + b) * T_ + t) * M_ + c]
                               : Xc[((size_t)(b0 + b) * T_ + t) * C_ + (c - 16)];
            xs[c * STP + b] = v;
        }

        // ---- stage chunk 0 into buf0 ----
        float pf[32];
        if (tid < 256) {
            const float* src = hp + (size_t)(b0 + sb) * H_ + skk;
#pragma unroll
            for (int i = 0; i < 32; i++) pf[i] = src[(size_t)(4 * i) * H_];
#pragma unroll
            for (int i = 0; i < 32; i++) buf0[skk * STP + sb + 4 * i] = pf[i];
        }
        __syncthreads();

        unsigned long long acc[4][2];
#pragma unroll
        for (int r = 0; r < 4; r++) { acc[r][0] = 0ull; acc[r][1] = 0ull; }

        for (int kc = 0; kc < 12; kc++) {
            const float* cur = (kc & 1) ? buf1 : buf0;
            float* nxt = (kc & 1) ? buf0 : buf1;
            // prefetch next chunk while computing this one
            if (kc < 11 && tid < 256) {
                const float* src = hp + (size_t)(b0 + sb) * H_ + (kc + 1) * 64 + skk;
#pragma unroll
                for (int i = 0; i < 32; i++) pf[i] = src[(size_t)(4 * i) * H_];
            }
            const unsigned* wr = (const unsigned*)(Ws + r0 * 768 + kc * 64);
            const float* stc = cur + 2 * tx;
#pragma unroll 8
            for (int kk = 0; kk < 64; kk++) {
                unsigned long long W0, W1, W2, W3;
                PACK2(W0, wr[kk]);        PACK2(W1, wr[768 + kk]);
                PACK2(W2, wr[1536 + kk]); PACK2(W3, wr[2304 + kk]);
                unsigned long long h01 = *(const unsigned long long*)(stc + kk * STP);
                unsigned long long h23 = *(const unsigned long long*)(stc + kk * STP + 64);
                FMA2(acc[0][0], W0, h01); FMA2(acc[0][1], W0, h23);
                FMA2(acc[1][0], W1, h01); FMA2(acc[1][1], W1, h23);
                FMA2(acc[2][0], W2, h01); FMA2(acc[2][1], W2, h23);
                FMA2(acc[3][0], W3, h01); FMA2(acc[3][1], W3, h23);
            }
            if (kc < 11 && tid < 256) {
#pragma unroll
                for (int i = 0; i < 32; i++) nxt[skk * STP + sb + 4 * i] = pf[i];
            }
            __syncthreads();
        }

        // ---- input-part (kept separate for the n gate) ----
        unsigned long long ax[4][2];
#pragma unroll
        for (int r = 0; r < 4; r++) { ax[r][0] = 0ull; ax[r][1] = 0ull; }
        {
            const unsigned* wir = (const unsigned*)(Wi + r0 * 32);
            const float* xsc = xs + 2 * tx;
#pragma unroll
            for (int c = 0; c < 32; c++) {
                unsigned long long W0, W1, W2, W3;
                PACK2(W0, wir[c]);      PACK2(W1, wir[32 + c]);
                PACK2(W2, wir[64 + c]); PACK2(W3, wir[96 + c]);
                unsigned long long x01 = *(const unsigned long long*)(xsc + c * STP);
                unsigned long long x23 = *(const unsigned long long*)(xsc + c * STP + 64);
                FMA2(ax[0][0], W0, x01); FMA2(ax[0][1], W0, x23);
                FMA2(ax[1][0], W1, x01); FMA2(ax[1][1], W1, x23);
                FMA2(ax[2][0], W2, x01); FMA2(ax[2][1], W2, x23);
                FMA2(ax[3][0], W3, x01); FMA2(ax[3][1], W3, x23);
            }
        }

        // ---- epilogue: write gate pre-activations to gb = buf0 ----
        // rows 0..23: r,z (combined); 24..35: n hidden-part(+bh); 36..47: n input-part(+bi)
        float* gb = buf0;
        const int bA = 2 * tx, bB = 64 + 2 * tx;
#pragma unroll
        for (int rr = 0; rr < 4; rr++) {
            int rl = r0 + rr;
            float a0, a1, a2, a3, x0, x1, x2, x3;
            UNPK2(a0, a1, acc[rr][0]); UNPK2(a2, a3, acc[rr][1]);
            UNPK2(x0, x1, ax[rr][0]);  UNPK2(x2, x3, ax[rr][1]);
            if (rl < 24) {
                float bb = bi[rl] + bh[rl];
                gb[rl * STP + bA]     = a0 + x0 + bb;
                gb[rl * STP + bA + 1] = a1 + x1 + bb;
                gb[rl * STP + bB]     = a2 + x2 + bb;
                gb[rl * STP + bB + 1] = a3 + x3 + bb;
            } else {
                float bhv = bh[rl], biv = bi[rl];
                gb[rl * STP + bA]     = a0 + bhv;
                gb[rl * STP + bA + 1] = a1 + bhv;
                gb[rl * STP + bB]     = a2 + bhv;
                gb[rl * STP + bB + 1] = a3 + bhv;
                gb[(rl + 12) * STP + bA]     = x0 + biv;
                gb[(rl + 12) * STP + bA + 1] = x1 + biv;
                gb[(rl + 12) * STP + bB]     = x2 + biv;
                gb[(rl + 12) * STP + bB + 1] = x3 + biv;
            }
        }
        __syncthreads();

        // ---- gate nonlinearity + state update ----
        for (int e = tid; e < HSL * 128; e += GT_) {
            int b = e / HSL, j = e - b * HSL;
            float rg  = sigmoidf_(gb[j * STP + b]);
            float zg  = sigmoidf_(gb[(12 + j) * STP + b]);
            float hn  = gb[(24 + j) * STP + b];
            float inn = gb[(36 + j) * STP + b];
            float n   = tanhf(inn + rg * hn);
            float hv  = hp[(size_t)(b0 + b) * H_ + j0 + j];
            ho[(size_t)(b0 + b) * H_ + j0 + j] = (1.f - zg) * n + zg * hv;
        }

        // ---- grid barrier (skip after last step) ----
        if (t < T_ - 1) {
            __threadfence();            // flush this thread's h writes (gpu scope)
            __syncthreads();
            if (tid == 0) {
                unsigned tgt = (unsigned)t + 1u;
                if (atomicAdd(&g_arrive, 1u) == 127u) {
                    g_arrive = 0u;
                    __threadfence();
                    *(volatile unsigned*)&g_release = tgt;
                } else {
                    while (*(volatile unsigned*)&g_release < tgt) { __nanosleep(32); }
                }
                __threadfence();        // acquire
            }
            __syncthreads();
        }
    }
}

// =====================================================================
// kernel 5: heads. One warp per 8 (b,t) items.
// =====================================================================
__global__ void __launch_bounds__(256, 1)
heads_kernel(const float* __restrict__ Xc,
             const float* __restrict__ wraw_w, const float* __restrict__ wraw_b,
             const float* __restrict__ ctrl_w, const float* __restrict__ ctrl_b,
             const float* __restrict__ reg_emb, const float* __restrict__ bias,
             float* __restrict__ out_y, float* __restrict__ out_w, float* __restrict__ out_c) {
    extern __shared__ float hsm[];
    float* sww = hsm;              // 16*768
    float* scw = sww + 12288;      // 768*16
    float* scb = scw + 12288;      // 768
    float* srg = scb + 768;        // 768
    float* swb = srg + 768;        // 16
    int tid = threadIdx.x;
    for (int e = tid; e < 12288; e += 256) { sww[e] = wraw_w[e]; scw[e] = ctrl_w[e]; }
    for (int e = tid; e < 768; e += 256) { scb[e] = ctrl_b[e]; srg[e] = reg_emb[e]; }
    if (tid < 16) swb[tid] = wraw_b[tid];
    __syncthreads();

    int wid = tid >> 5, lane = tid & 31;
    float bias0 = bias[0];

    float rp = 0.f;
#pragma unroll
    for (int i = 0; i < 24; i++) rp += srg[lane + 32 * i];
    rp = wredux(rp) * 0.3f;

    for (int it = 0; it < 8; it++) {
        int n = blockIdx.x * 64 + wid * 8 + it;   // < 131072
        int b = n >> 9, t = n & 511;

        const float* hrow = g_hseq + (size_t)(t + 1) * BH_ + (size_t)b * H_;
        float hv[24];
#pragma unroll
        for (int i = 0; i < 24; i++) hv[i] = hrow[lane + 32 * i];
        float wp[16];
#pragma unroll
        for (int m = 0; m < 16; m++) {
            float p = 0.f;
#pragma unroll
            for (int i = 0; i < 24; i++) p += hv[i] * sww[m * 768 + lane + 32 * i];
            p = wredux(p);
            wp[m] = softplusf_(p + swb[m]);
        }
        if (t == 0) {
            const float* h2 = g_hseq + (size_t)2 * BH_ + (size_t)b * H_;
            float h2v[24];
#pragma unroll
            for (int i = 0; i < 24; i++) h2v[i] = h2[lane + 32 * i];
#pragma unroll
            for (int m = 0; m < 16; m++) {
                float p = 0.f;
#pragma unroll
                for (int i = 0; i < 24; i++) p += h2v[i] * sww[m * 768 + lane + 32 * i];
                p = wredux(p);
                wp[m] = 0.5f * softplusf_(p + swb[m]) + 0.5f * wp[m];
            }
        }

        float media = 0.f;
        const float* hillrow = g_hill + ((size_t)b * T_ + t) * M_;
        float cb[16];
#pragma unroll
        for (int m = 0; m < 16; m++) { cb[m] = hillrow[m] * wp[m]; media += cb[m]; }

        float xc[16];
#pragma unroll
        for (int c = 0; c < 16; c++) xc[c] = Xc[((size_t)b * T_ + t) * C_ + c];
        float ct = 0.f;
#pragma unroll
        for (int i = 0; i < 24; i++) {
            int j = lane + 32 * i;
            float s = scb[j];
#pragma unroll
            for (int c = 0; c < 16; c++) s += xc[c] * scw[j * 16 + c];
            ct += fmaxf(s, 0.f);
        }
        ct = wredux(ct) * 0.3f;

        float y = media + ct + rp + bias0;
        if (lane == 0) out_y[(size_t)b * T_ + t] = y;
        if (out_w && lane < 16) out_w[((size_t)b * T_ + t) * M_ + lane] = wp[lane];
        if (out_c && lane < 16) out_c[((size_t)b * T_ + t) * M_ + lane] = cb[lane];
    }
}

// =====================================================================
// launch
// =====================================================================
extern "C" void kernel_launch(void* const* d_in, const int* in_sizes, int n_in,
                              void* d_out, int out_size) {
    const float* Xm     = (const float*)d_in[0];
    const float* Xc     = (const float*)d_in[1];
    /* d_in[2] = R (int32) unused in forward */
    const float* A      = (const float*)d_in[3];
    const float* ew1    = (const float*)d_in[4];
    const float* eb1    = (const float*)d_in[5];
    const float* ew2    = (const float*)d_in[6];
    const float* eb2    = (const float*)d_in[7];
    const float* nw     = (const float*)d_in[8];
    const float* nb     = (const float*)d_in[9];
    const float* W_ih   = (const float*)d_in[10];
    const float* W_hh   = (const float*)d_in[11];
    const float* b_ih   = (const float*)d_in[12];
    const float* b_hh   = (const float*)d_in[13];
    const float* wraw_w = (const float*)d_in[14];
    const float* wraw_b = (const float*)d_in[15];
    const float* alpha  = (const float*)d_in[16];
    const float* hill_a = (const float*)d_in[17];
    const float* hill_g = (const float*)d_in[18];
    const float* ctrl_w = (const float*)d_in[19];
    const float* ctrl_b = (const float*)d_in[20];
    const float* regemb = (const float*)d_in[21];
    const float* bias   = (const float*)d_in[22];
    const float* h0     = (const float*)d_in[23];

    const int GRU_SMEM  = (27648 + 1152 + 40 + 40 + 4160 + 8320 + 8320) * 4;  // 198720
    const int HEAD_SMEM = (12288 + 12288 + 768 + 768 + 16) * 4;               // 104512
    cudaFuncSetAttribute(gru_persist_kernel, cudaFuncAttributeMaxDynamicSharedMemorySize, GRU_SMEM);
    cudaFuncSetAttribute(heads_kernel, cudaFuncAttributeMaxDynamicSharedMemorySize, HEAD_SMEM);

    enc_kernel<<<BT_ / 256, 256>>>(Xm, A, ew1, eb1, ew2, eb2, nw, nb);
    adstock_kernel<<<(B_ * M_) / 256, 256>>>(Xm, alpha, hill_a, hill_g);
    hinit_kernel<<<BH_ / 256, 256>>>(h0);

    gru_persist_kernel<<<128, GT_, GRU_SMEM>>>(Xc, W_ih, W_hh, b_ih, b_hh);

    float* out = (float*)d_out;
    float* oy = out;
    float* ow = nullptr;
    float* oc = nullptr;
    if (out_size >= BT_ + 2 * BTM_) { ow = out + BT_; oc = out + BT_ + BTM_; }
    else if (out_size >= BT_ + BTM_) { ow = out + BT_; }

    heads_kernel<<<BT_ / 64, 256, HEAD_SMEM>>>(Xc, wraw_w, wraw_b, ctrl_w, ctrl_b,
                                               regemb, bias, oy, ow, oc);
}

// round 11
// speedup vs baseline: 1.9591x; 1.0025x over previous
#include <cuda_runtime.h>
#include <math.h>

// ---------------- problem constants ----------------
#define B_ 256
#define T_ 512
#define M_ 16
#define C_ 16
#define H_ 768
#define BT_  (B_ * T_)           // 131072
#define BTM_ (BT_ * M_)          // 2097152
#define BH_  (B_ * H_)           // 196608

// ---------------- GRU partition ----------------
#define GT_   288                // threads per GRU CTA (9 warps)
#define SROWS 36                 // 3 gates x 12 hidden units
#define HSL   12                 // hidden units per CTA
#define STP   130                // padded batch stride (even -> LDS.64 aligned)

// ---------------- scratch (static device memory; no allocs) ----------------
__device__ float g_Z[BTM_];
__device__ float g_hill[BTM_];
__device__ float g_xin[BTM_];
__device__ float g_hseq[100859904];   // (T_+1) * B_ * H_ = 513*256*768
__device__ unsigned g_arrive;
__device__ unsigned g_release;

// ---------------- helpers ----------------
__device__ __forceinline__ float sigmoidf_(float x) { return 1.0f / (1.0f + expf(-x)); }
__device__ __forceinline__ float softplusf_(float x) {
    return fmaxf(x, 0.0f) + log1pf(expf(-fabsf(x)));
}
__device__ __forceinline__ float wredux(float v) {
#pragma unroll
    for (int off = 16; off; off >>= 1) v += __shfl_xor_sync(0xffffffffu, v, off);
    return v;
}

// packed fp32x2 ops (Blackwell FFMA2 — PTX only)
#define FMA2(acc, a, b) asm("fma.rn.f32x2 %0, %1, %2, %3;" : "=l"(acc) : "l"(a), "l"(b), "l"(acc))
#define PACK2(d, s)     asm("mov.b64 %0, {%1, %1};" : "=l"(d) : "r"(s))
#define UNPK2(lo, hi, v) asm("mov.b64 {%0, %1}, %2;" : "=f"(lo), "=f"(hi) : "l"(v))

// =====================================================================
// kernel 1: causal encoder -> g_Z   (one thread per (b,t))
// =====================================================================
__global__ void __launch_bounds__(256)
enc_kernel(const float* __restrict__ Xm, const float* __restrict__ A,
           const float* __restrict__ ew1, const float* __restrict__ eb1,
           const float* __restrict__ ew2, const float* __restrict__ eb2,
           const float* __restrict__ nw, const float* __restrict__ nb) {
    __shared__ float sA[256], sw1[512], sw2[256], snw[512];
    __shared__ float sb1[16], sb2[16], snb[16];
    int tid = threadIdx.x;
    sA[tid] = A[tid];
    sw2[tid] = ew2[tid];
    sw1[tid] = ew1[tid];       sw1[tid + 256] = ew1[tid + 256];
    snw[tid] = nw[tid];        snw[tid + 256] = nw[tid + 256];
    if (tid < 16) { sb1[tid] = eb1[tid]; sb2[tid] = eb2[tid]; snb[tid] = nb[tid]; }
    __syncthreads();

    int idx = blockIdx.x * 256 + tid;      // b*T + t
    float x[16];
#pragma unroll
    for (int j = 0; j < 16; j++) x[j] = Xm[(size_t)idx * 16 + j];

    float send[16], recv[16];
#pragma unroll
    for (int i = 0; i < 16; i++) {
        float s = 0.f, r = 0.f;
#pragma unroll
        for (int j = 0; j < 16; j++) { s += x[j] * sA[i * 16 + j]; r += x[j] * sA[j * 16 + i]; }
        send[i] = s; recv[i] = r;
    }
    float h1[16];
#pragma unroll
    for (int i = 0; i < 16; i++) {
        float s = sb1[i];
#pragma unroll
        for (int j = 0; j < 16; j++)
            s += send[j] * sw1[i * 32 + j] + recv[j] * sw1[i * 32 + 16 + j];
        h1[i] = fmaxf(s, 0.f);
    }
    float h2[16];
#pragma unroll
    for (int i = 0; i < 16; i++) {
        float s = sb2[i];
#pragma unroll
        for (int j = 0; j < 16; j++) s += h1[j] * sw2[i * 16 + j];
        h2[i] = fmaxf(s, 0.f);
    }
#pragma unroll
    for (int i = 0; i < 16; i++) {
        float s = snb[i];
#pragma unroll
        for (int j = 0; j < 16; j++)
            s += x[j] * snw[i * 32 + j] + h2[j] * snw[i * 32 + 16 + j];
        g_Z[(size_t)idx * 16 + i] = fmaxf(s, 0.f);
    }
}

// =====================================================================
// kernel 2: adstock + hill; g_xin = hill + Z   (one thread per (b,m))
// =====================================================================
__global__ void __launch_bounds__(256)
adstock_kernel(const float* __restrict__ Xm, const float* __restrict__ alpha,
               const float* __restrict__ hill_a, const float* __restrict__ hill_g) {
    int tid = blockIdx.x * blockDim.x + threadIdx.x;   // < B*M
    int b = tid >> 4, m = tid & 15;
    float a  = fminf(fmaxf(alpha[m], 0.0f), 1.0f);
    float ha = fminf(fmaxf(hill_a[m], 0.1f), 3.0f);
    float hg = fminf(fmaxf(hill_g[m], 0.1f), 2.0f);
    float hga = powf(hg, ha);

    const float* xm = Xm + (size_t)b * T_ * M_ + m;
    float* hil = g_hill + (size_t)b * T_ * M_ + m;
    float* xin = g_xin + (size_t)b * T_ * M_ + m;
    const float* zp = g_Z + (size_t)b * T_ * M_ + m;

    float prev = 0.f, cmax = -1e30f;
    for (int t = 0; t < T_; t++) {
        float cur = xm[t * M_] + a * prev;
        prev = cur;
        hil[t * M_] = cur;
        cmax = fmaxf(cmax, cur);
    }
    cmax = fmaxf(cmax, 1e-6f);
    float inv = 1.0f / cmax;
    for (int t = 0; t < T_; t++) {
        float xn = fmaxf(hil[t * M_] * inv, 0.0f);
        float num = powf(xn, ha);
        float h = num / (num + hga + 1e-8f);
        hil[t * M_] = h;
        xin[t * M_] = h + zp[t * M_];
    }
}

// =====================================================================
// kernel 3: h0 broadcast into slot 0 of g_hseq + barrier reset
// =====================================================================
__global__ void __launch_bounds__(256)
hinit_kernel(const float* __restrict__ h0) {
    int idx = blockIdx.x * 256 + threadIdx.x;     // < B*H
    if (idx == 0) { g_arrive = 0u; g_release = 0u; }
    int j = idx % H_;
    g_hseq[idx] = h0[j];
}

// =====================================================================
// kernel 4: persistent GRU — all 512 steps in one kernel.
// 128 CTAs = 2 batch-tiles x 64 hidden-slices; weights resident in smem;
// double-buffered h staging; packed f32x2 FMA; grid barrier per step.
// Thread (tx,ty): gate rows r0..r0+3 (r0=4*ty), batches {2tx,2tx+1,64+2tx,64+2tx+1}.
// =====================================================================
extern __shared__ float g_sm[];

__global__ void __launch_bounds__(GT_, 1)
gru_persist_kernel(const float* __restrict__ Xc,
                   const float* __restrict__ W_ih, const float* __restrict__ W_hh,
                   const float* __restrict__ b_ih, const float* __restrict__ b_hh) {
    float* Ws   = g_sm;              // [36][768]        27648
    float* Wi   = Ws + 27648;        // [36][32]          1152
    float* bi   = Wi + 1152;         // [40]
    float* bh   = bi + 40;           // [40]
    float* xs   = bh + 40;           // [32][130]         4160
    float* buf0 = xs + 4160;         // [64][130]         8320
    float* buf1 = buf0 + 8320;       // [64][130]         8320
    // total 49680 floats = 198720 B

    const int tid = threadIdx.x;
    const int tx = tid & 31, ty = tid >> 5;     // ty 0..8
    const int bt = blockIdx.x >> 6;             // 0..1
    const int hs = blockIdx.x & 63;             // 0..63
    const int j0 = hs * HSL;
    const int b0 = bt * 128;
    const int r0 = ty * 4;

    // ---- load weight slices ONCE ----
    for (int e = tid; e < SROWS * 768; e += GT_) {
        int r = e / 768, k = e - r * 768;
        int grow = (r < 12) ? (j0 + r) : (r < 24) ? (H_ + j0 + r - 12) : (2 * H_ + j0 + r - 24);
        Ws[e] = W_hh[(size_t)grow * H_ + k];
    }
    for (int e = tid; e < SROWS * 32; e += GT_) {
        int r = e >> 5, c = e & 31;
        int grow = (r < 12) ? (j0 + r) : (r < 24) ? (H_ + j0 + r - 12) : (2 * H_ + j0 + r - 24);
        Wi[e] = W_ih[grow * 32 + c];
    }
    if (tid < SROWS) {
        int r = tid;
        int grow = (r < 12) ? (j0 + r) : (r < 24) ? (H_ + j0 + r - 12) : (2 * H_ + j0 + r - 24);
        bi[r] = b_ih[grow]; bh[r] = b_hh[grow];
    }

    const int skk = tid & 63;   // staging column (k within chunk)
    const int sb  = tid >> 6;   // staging batch base (0..3), valid for tid<256

    for (int t = 0; t < T_; t++) {
        const float* hp = g_hseq + (size_t)t * BH_;
        float* ho = g_hseq + (size_t)(t + 1) * BH_;

        // ---- stage x = concat(hill+Z, Xc) : xs[c][b] ----
        for (int e = tid; e < 32 * 128; e += GT_) {
            int c = e >> 7, b = e & 127;
            float v = (c < 16) ? g_xin[((size_t)(b0 + b) * T_ + t) * M_ + c]
                               : Xc[((size_t)(b0 + b) * T_ + t) * C_ + (c - 16)];
            xs[c * STP + b] = v;
        }

        // ---- stage chunk 0 into buf0 ----
        float pf[32];
        if (tid < 256) {
            const float* src = hp + (size_t)(b0 + sb) * H_ + skk;
#pragma unroll
            for (int i = 0; i < 32; i++) pf[i] = src[(size_t)(4 * i) * H_];
#pragma unroll
            for (int i = 0; i < 32; i++) buf0[skk * STP + sb + 4 * i] = pf[i];
        }
        __syncthreads();

        unsigned long long acc[4][2];
#pragma unroll
        for (int r = 0; r < 4; r++) { acc[r][0] = 0ull; acc[r][1] = 0ull; }

        for (int kc = 0; kc < 12; kc++) {
            const float* cur = (kc & 1) ? buf1 : buf0;
            float* nxt = (kc & 1) ? buf0 : buf1;
            // prefetch next chunk while computing this one
            if (kc < 11 && tid < 256) {
                const float* src = hp + (size_t)(b0 + sb) * H_ + (kc + 1) * 64 + skk;
#pragma unroll
                for (int i = 0; i < 32; i++) pf[i] = src[(size_t)(4 * i) * H_];
            }
            const unsigned* wr = (const unsigned*)(Ws + r0 * 768 + kc * 64);
            const float* stc = cur + 2 * tx;
#pragma unroll 8
            for (int kk = 0; kk < 64; kk++) {
                unsigned long long W0, W1, W2, W3;
                PACK2(W0, wr[kk]);        PACK2(W1, wr[768 + kk]);
                PACK2(W2, wr[1536 + kk]); PACK2(W3, wr[2304 + kk]);
                unsigned long long h01 = *(const unsigned long long*)(stc + kk * STP);
                unsigned long long h23 = *(const unsigned long long*)(stc + kk * STP + 64);
                FMA2(acc[0][0], W0, h01); FMA2(acc[0][1], W0, h23);
                FMA2(acc[1][0], W1, h01); FMA2(acc[1][1], W1, h23);
                FMA2(acc[2][0], W2, h01); FMA2(acc[2][1], W2, h23);
                FMA2(acc[3][0], W3, h01); FMA2(acc[3][1], W3, h23);
            }
            if (kc < 11 && tid < 256) {
#pragma unroll
                for (int i = 0; i < 32; i++) nxt[skk * STP + sb + 4 * i] = pf[i];
            }
            __syncthreads();
        }

        // ---- input-part (kept separate for the n gate) ----
        unsigned long long ax[4][2];
#pragma unroll
        for (int r = 0; r < 4; r++) { ax[r][0] = 0ull; ax[r][1] = 0ull; }
        {
            const unsigned* wir = (const unsigned*)(Wi + r0 * 32);
            const float* xsc = xs + 2 * tx;
#pragma unroll
            for (int c = 0; c < 32; c++) {
                unsigned long long W0, W1, W2, W3;
                PACK2(W0, wir[c]);      PACK2(W1, wir[32 + c]);
                PACK2(W2, wir[64 + c]); PACK2(W3, wir[96 + c]);
                unsigned long long x01 = *(const unsigned long long*)(xsc + c * STP);
                unsigned long long x23 = *(const unsigned long long*)(xsc + c * STP + 64);
                FMA2(ax[0][0], W0, x01); FMA2(ax[0][1], W0, x23);
                FMA2(ax[1][0], W1, x01); FMA2(ax[1][1], W1, x23);
                FMA2(ax[2][0], W2, x01); FMA2(ax[2][1], W2, x23);
                FMA2(ax[3][0], W3, x01); FMA2(ax[3][1], W3, x23);
            }
        }

        // ---- epilogue: write gate pre-activations to gb = buf0 ----
        // rows 0..23: r,z (combined); 24..35: n hidden-part(+bh); 36..47: n input-part(+bi)
        float* gb = buf0;
        const int bA = 2 * tx, bB = 64 + 2 * tx;
#pragma unroll
        for (int rr = 0; rr < 4; rr++) {
            int rl = r0 + rr;
            float a0, a1, a2, a3, x0, x1, x2, x3;
            UNPK2(a0, a1, acc[rr][0]); UNPK2(a2, a3, acc[rr][1]);
            UNPK2(x0, x1, ax[rr][0]);  UNPK2(x2, x3, ax[rr][1]);
            if (rl < 24) {
                float bb = bi[rl] + bh[rl];
                gb[rl * STP + bA]     = a0 + x0 + bb;
                gb[rl * STP + bA + 1] = a1 + x1 + bb;
                gb[rl * STP + bB]     = a2 + x2 + bb;
                gb[rl * STP + bB + 1] = a3 + x3 + bb;
            } else {
                float bhv = bh[rl], biv = bi[rl];
                gb[rl * STP + bA]     = a0 + bhv;
                gb[rl * STP + bA + 1] = a1 + bhv;
                gb[rl * STP + bB]     = a2 + bhv;
                gb[rl * STP + bB + 1] = a3 + bhv;
                gb[(rl + 12) * STP + bA]     = x0 + biv;
                gb[(rl + 12) * STP + bA + 1] = x1 + biv;
                gb[(rl + 12) * STP + bB]     = x2 + biv;
                gb[(rl + 12) * STP + bB + 1] = x3 + biv;
            }
        }
        __syncthreads();

        // ---- gate nonlinearity + state update ----
        for (int e = tid; e < HSL * 128; e += GT_) {
            int b = e / HSL, j = e - b * HSL;
            float rg  = sigmoidf_(gb[j * STP + b]);
            float zg  = sigmoidf_(gb[(12 + j) * STP + b]);
            float hn  = gb[(24 + j) * STP + b];
            float inn = gb[(36 + j) * STP + b];
            float n   = tanhf(inn + rg * hn);
            float hv  = hp[(size_t)(b0 + b) * H_ + j0 + j];
            ho[(size_t)(b0 + b) * H_ + j0 + j] = (1.f - zg) * n + zg * hv;
        }

        // ---- grid barrier (skip after last step) ----
        if (t < T_ - 1) {
            __threadfence();            // flush this thread's h writes (gpu scope)
            __syncthreads();
            if (tid == 0) {
                unsigned tgt = (unsigned)t + 1u;
                if (atomicAdd(&g_arrive, 1u) == 127u) {
                    g_arrive = 0u;
                    __threadfence();
                    *(volatile unsigned*)&g_release = tgt;
                } else {
                    while (*(volatile unsigned*)&g_release < tgt) { __nanosleep(32); }
                }
                __threadfence();        // acquire
            }
            __syncthreads();
        }
    }
}

// =====================================================================
// kernel 5: heads. One warp per 8 (b,t) items.
// =====================================================================
__global__ void __launch_bounds__(256, 1)
heads_kernel(const float* __restrict__ Xc,
             const float* __restrict__ wraw_w, const float* __restrict__ wraw_b,
             const float* __restrict__ ctrl_w, const float* __restrict__ ctrl_b,
             const float* __restrict__ reg_emb, const float* __restrict__ bias,
             float* __restrict__ out_y, float* __restrict__ out_w, float* __restrict__ out_c) {
    extern __shared__ float hsm[];
    float* sww = hsm;              // 16*768
    float* scw = sww + 12288;      // 768*16
    float* scb = scw + 12288;      // 768
    float* srg = scb + 768;        // 768
    float* swb = srg + 768;        // 16
    int tid = threadIdx.x;
    for (int e = tid; e < 12288; e += 256) { sww[e] = wraw_w[e]; scw[e] = ctrl_w[e]; }
    for (int e = tid; e < 768; e += 256) { scb[e] = ctrl_b[e]; srg[e] = reg_emb[e]; }
    if (tid < 16) swb[tid] = wraw_b[tid];
    __syncthreads();

    int wid = tid >> 5, lane = tid & 31;
    float bias0 = bias[0];

    float rp = 0.f;
#pragma unroll
    for (int i = 0; i < 24; i++) rp += srg[lane + 32 * i];
    rp = wredux(rp) * 0.3f;

    for (int it = 0; it < 8; it++) {
        int n = blockIdx.x * 64 + wid * 8 + it;   // < 131072
        int b = n >> 9, t = n & 511;

        const float* hrow = g_hseq + (size_t)(t + 1) * BH_ + (size_t)b * H_;
        float hv[24];
#pragma unroll
        for (int i = 0; i < 24; i++) hv[i] = hrow[lane + 32 * i];
        float wp[16];
#pragma unroll
        for (int m = 0; m < 16; m++) {
            float p = 0.f;
#pragma unroll
            for (int i = 0; i < 24; i++) p += hv[i] * sww[m * 768 + lane + 32 * i];
            p = wredux(p);
            wp[m] = softplusf_(p + swb[m]);
        }
        if (t == 0) {
            const float* h2 = g_hseq + (size_t)2 * BH_ + (size_t)b * H_;
            float h2v[24];
#pragma unroll
            for (int i = 0; i < 24; i++) h2v[i] = h2[lane + 32 * i];
#pragma unroll
            for (int m = 0; m < 16; m++) {
                float p = 0.f;
#pragma unroll
                for (int i = 0; i < 24; i++) p += h2v[i] * sww[m * 768 + lane + 32 * i];
                p = wredux(p);
                wp[m] = 0.5f * softplusf_(p + swb[m]) + 0.5f * wp[m];
            }
        }

        float media = 0.f;
        const float* hillrow = g_hill + ((size_t)b * T_ + t) * M_;
        float cb[16];
#pragma unroll
        for (int m = 0; m < 16; m++) { cb[m] = hillrow[m] * wp[m]; media += cb[m]; }

        float xc[16];
#pragma unroll
        for (int c = 0; c < 16; c++) xc[c] = Xc[((size_t)b * T_ + t) * C_ + c];
        float ct = 0.f;
#pragma unroll
        for (int i = 0; i < 24; i++) {
            int j = lane + 32 * i;
            float s = scb[j];
#pragma unroll
            for (int c = 0; c < 16; c++) s += xc[c] * scw[j * 16 + c];
            ct += fmaxf(s, 0.f);
        }
        ct = wredux(ct) * 0.3f;

        float y = media + ct + rp + bias0;
        if (lane == 0) out_y[(size_t)b * T_ + t] = y;
        if (out_w && lane < 16) out_w[((size_t)b * T_ + t) * M_ + lane] = wp[lane];
        if (out_c && lane < 16) out_c[((size_t)b * T_ + t) * M_ + lane] = cb[lane];
    }
}

// =====================================================================
// launch
// =====================================================================
extern "C" void kernel_launch(void* const* d_in, const int* in_sizes, int n_in,
                              void* d_out, int out_size) {
    const float* Xm     = (const float*)d_in[0];
    const float* Xc     = (const float*)d_in[1];
    /* d_in[2] = R (int32) unused in forward */
    const float* A      = (const float*)d_in[3];
    const float* ew1    = (const float*)d_in[4];
    const float* eb1    = (const float*)d_in[5];
    const float* ew2    = (const float*)d_in[6];
    const float* eb2    = (const float*)d_in[7];
    const float* nw     = (const float*)d_in[8];
    const float* nb     = (const float*)d_in[9];
    const float* W_ih   = (const float*)d_in[10];
    const float* W_hh   = (const float*)d_in[11];
    const float* b_ih   = (const float*)d_in[12];
    const float* b_hh   = (const float*)d_in[13];
    const float* wraw_w = (const float*)d_in[14];
    const float* wraw_b = (const float*)d_in[15];
    const float* alpha  = (const float*)d_in[16];
    const float* hill_a = (const float*)d_in[17];
    const float* hill_g = (const float*)d_in[18];
    const float* ctrl_w = (const float*)d_in[19];
    const float* ctrl_b = (const float*)d_in[20];
    const float* regemb = (const float*)d_in[21];
    const float* bias   = (const float*)d_in[22];
    const float* h0     = (const float*)d_in[23];

    const int GRU_SMEM  = (27648 + 1152 + 40 + 40 + 4160 + 8320 + 8320) * 4;  // 198720
    const int HEAD_SMEM = (12288 + 12288 + 768 + 768 + 16) * 4;               // 104512
    cudaFuncSetAttribute(gru_persist_kernel, cudaFuncAttributeMaxDynamicSharedMemorySize, GRU_SMEM);
    cudaFuncSetAttribute(heads_kernel, cudaFuncAttributeMaxDynamicSharedMemorySize, HEAD_SMEM);

    enc_kernel<<<BT_ / 256, 256>>>(Xm, A, ew1, eb1, ew2, eb2, nw, nb);
    adstock_kernel<<<(B_ * M_) / 256, 256>>>(Xm, alpha, hill_a, hill_g);
    hinit_kernel<<<BH_ / 256, 256>>>(h0);

    gru_persist_kernel<<<128, GT_, GRU_SMEM>>>(Xc, W_ih, W_hh, b_ih, b_hh);

    float* out = (float*)d_out;
    float* oy = out;
    float* ow = nullptr;
    float* oc = nullptr;
    if (out_size >= BT_ + 2 * BTM_) { ow = out + BT_; oc = out + BT_ + BTM_; }
    else if (out_size >= BT_ + BTM_) { ow = out + BT_; }

    heads_kernel<<<BT_ / 64, 256, HEAD_SMEM>>>(Xc, wraw_w, wraw_b, ctrl_w, ctrl_b,
                                               regemb, bias, oy, ow, oc);
}

// round 12
// speedup vs baseline: 2.4267x; 1.2387x over previous
#include <cuda_runtime.h>
#include <math.h>

// ---------------- problem constants ----------------
#define B_ 256
#define T_ 512
#define M_ 16
#define C_ 16
#define H_ 768
#define BT_  (B_ * T_)
#define BTM_ (BT_ * M_)
#define BH_  (B_ * H_)

// ---------------- GRU partition ----------------
#define GT_   256                // 8 warps
#define SROWS 36
#define HSL   12
#define RPW   9                  // rows per warp
#define STP   68                 // h chunk stride [b][68]
#define XSP   36                 // x stride [b][36]
#define GBS   130                // gate buffer stride

// smem offsets (floats)
#define OFF_WS   0
#define OFF_WI   27648
#define OFF_BI   28800
#define OFF_BH   28840
#define OFF_XS   28880           // [128][36] = 4608
#define OFF_STA  33488           // [128][68] = 8704
#define OFF_STB  42192           // [128][68] = 8704
#define SM_FLOATS 50896

// ---------------- scratch ----------------
__device__ float g_Z[BTM_];
__device__ float g_hill[BTM_];
__device__ float g_xin[BTM_];
__device__ float g_hseq[100859904];   // (T_+1)*B_*H_
__device__ unsigned g_arrive;
__device__ unsigned g_release;

// ---------------- helpers ----------------
__device__ __forceinline__ float sigmoidf_(float x) { return 1.0f / (1.0f + expf(-x)); }
__device__ __forceinline__ float softplusf_(float x) {
    return fmaxf(x, 0.0f) + log1pf(expf(-fabsf(x)));
}
__device__ __forceinline__ float wredux(float v) {
#pragma unroll
    for (int off = 16; off; off >>= 1) v += __shfl_xor_sync(0xffffffffu, v, off);
    return v;
}
#define FMA2(acc, a, b) asm("fma.rn.f32x2 %0, %1, %2, %3;" : "=l"(acc) : "l"(a), "l"(b), "l"(acc))
__device__ __forceinline__ float usum_(unsigned long long v) {
    float lo, hi; asm("mov.b64 {%0, %1}, %2;" : "=f"(lo), "=f"(hi) : "l"(v)); return lo + hi;
}
#define CP_ASYNC16(dst, src) \
    asm volatile("cp.async.cg.shared.global [%0], [%1], 16;" :: \
                 "r"((unsigned)__cvta_generic_to_shared(dst)), "l"(src) : "memory")
#define CP_COMMIT()  asm volatile("cp.async.commit_group;" ::: "memory")
#define CP_WAIT0()   asm volatile("cp.async.wait_group 0;" ::: "memory")

// =====================================================================
// kernel 1: causal encoder -> g_Z
// =====================================================================
__global__ void __launch_bounds__(256)
enc_kernel(const float* __restrict__ Xm, const float* __restrict__ A,
           const float* __restrict__ ew1, const float* __restrict__ eb1,
           const float* __restrict__ ew2, const float* __restrict__ eb2,
           const float* __restrict__ nw, const float* __restrict__ nb) {
    __shared__ float sA[256], sw1[512], sw2[256], snw[512];
    __shared__ float sb1[16], sb2[16], snb[16];
    int tid = threadIdx.x;
    sA[tid] = A[tid];
    sw2[tid] = ew2[tid];
    sw1[tid] = ew1[tid];       sw1[tid + 256] = ew1[tid + 256];
    snw[tid] = nw[tid];        snw[tid + 256] = nw[tid + 256];
    if (tid < 16) { sb1[tid] = eb1[tid]; sb2[tid] = eb2[tid]; snb[tid] = nb[tid]; }
    __syncthreads();

    int idx = blockIdx.x * 256 + tid;
    float x[16];
#pragma unroll
    for (int j = 0; j < 16; j++) x[j] = Xm[(size_t)idx * 16 + j];

    float send[16], recv[16];
#pragma unroll
    for (int i = 0; i < 16; i++) {
        float s = 0.f, r = 0.f;
#pragma unroll
        for (int j = 0; j < 16; j++) { s += x[j] * sA[i * 16 + j]; r += x[j] * sA[j * 16 + i]; }
        send[i] = s; recv[i] = r;
    }
    float h1[16];
#pragma unroll
    for (int i = 0; i < 16; i++) {
        float s = sb1[i];
#pragma unroll
        for (int j = 0; j < 16; j++)
            s += send[j] * sw1[i * 32 + j] + recv[j] * sw1[i * 32 + 16 + j];
        h1[i] = fmaxf(s, 0.f);
    }
    float h2[16];
#pragma unroll
    for (int i = 0; i < 16; i++) {
        float s = sb2[i];
#pragma unroll
        for (int j = 0; j < 16; j++) s += h1[j] * sw2[i * 16 + j];
        h2[i] = fmaxf(s, 0.f);
    }
#pragma unroll
    for (int i = 0; i < 16; i++) {
        float s = snb[i];
#pragma unroll
        for (int j = 0; j < 16; j++)
            s += x[j] * snw[i * 32 + j] + h2[j] * snw[i * 32 + 16 + j];
        g_Z[(size_t)idx * 16 + i] = fmaxf(s, 0.f);
    }
}

// =====================================================================
// kernel 2: adstock + hill; g_xin = hill + Z
// =====================================================================
__global__ void __launch_bounds__(256)
adstock_kernel(const float* __restrict__ Xm, const float* __restrict__ alpha,
               const float* __restrict__ hill_a, const float* __restrict__ hill_g) {
    int tid = blockIdx.x * blockDim.x + threadIdx.x;
    int b = tid >> 4, m = tid & 15;
    float a  = fminf(fmaxf(alpha[m], 0.0f), 1.0f);
    float ha = fminf(fmaxf(hill_a[m], 0.1f), 3.0f);
    float hg = fminf(fmaxf(hill_g[m], 0.1f), 2.0f);
    float hga = powf(hg, ha);

    const float* xm = Xm + (size_t)b * T_ * M_ + m;
    float* hil = g_hill + (size_t)b * T_ * M_ + m;
    float* xin = g_xin + (size_t)b * T_ * M_ + m;
    const float* zp = g_Z + (size_t)b * T_ * M_ + m;

    float prev = 0.f, cmax = -1e30f;
    for (int t = 0; t < T_; t++) {
        float cur = xm[t * M_] + a * prev;
        prev = cur;
        hil[t * M_] = cur;
        cmax = fmaxf(cmax, cur);
    }
    cmax = fmaxf(cmax, 1e-6f);
    float inv = 1.0f / cmax;
    for (int t = 0; t < T_; t++) {
        float xn = fmaxf(hil[t * M_] * inv, 0.0f);
        float num = powf(xn, ha);
        float h = num / (num + hga + 1e-8f);
        hil[t * M_] = h;
        xin[t * M_] = h + zp[t * M_];
    }
}

// =====================================================================
// kernel 3: h0 broadcast + barrier reset
// =====================================================================
__global__ void __launch_bounds__(256)
hinit_kernel(const float* __restrict__ h0) {
    int idx = blockIdx.x * 256 + threadIdx.x;
    if (idx == 0) { g_arrive = 0u; g_release = 0u; }
    int j = idx % H_;
    g_hseq[idx] = h0[j];
}

// =====================================================================
// kernel 4: persistent GRU. 128 CTAs = 2 batch-tiles x 64 hidden-slices.
// 8 warps = 4 row-groups(9 rows) x 2 k-groups. Batch-major h staging via
// cp.async double buffer; dot-trick f32x2 (lanes = even/odd k partials).
// =====================================================================
extern __shared__ float g_sm[];

__global__ void __launch_bounds__(GT_, 1)
gru_persist_kernel(const float* __restrict__ Xc,
                   const float* __restrict__ W_ih, const float* __restrict__ W_hh,
                   const float* __restrict__ b_ih, const float* __restrict__ b_hh) {
    float* Ws  = g_sm + OFF_WS;
    float* Wi  = g_sm + OFF_WI;
    float* bi  = g_sm + OFF_BI;
    float* bh  = g_sm + OFF_BH;
    float* xs  = g_sm + OFF_XS;
    float* stA = g_sm + OFF_STA;
    float* stB = g_sm + OFF_STB;

    const int tid = threadIdx.x;
    const int tx = tid & 31, wid = tid >> 5;
    const int rg = wid & 3;              // row group 0..3
    const int kg = wid >> 2;             // k group 0..1
    const int r0 = rg * RPW;
    const int kgofs = kg * 32;
    const int bt = blockIdx.x >> 6;
    const int hs = blockIdx.x & 63;
    const int j0 = hs * HSL;
    const int b0 = bt * 128;

    // ---- load weight slices ONCE ----
    for (int e = tid; e < SROWS * 768; e += GT_) {
        int r = e / 768, k = e - r * 768;
        int grow = (r < 12) ? (j0 + r) : (r < 24) ? (H_ + j0 + r - 12) : (2 * H_ + j0 + r - 24);
        Ws[e] = W_hh[(size_t)grow * H_ + k];
    }
    for (int e = tid; e < SROWS * 32; e += GT_) {
        int r = e >> 5, c = e & 31;
        int grow = (r < 12) ? (j0 + r) : (r < 24) ? (H_ + j0 + r - 12) : (2 * H_ + j0 + r - 24);
        Wi[e] = W_ih[grow * 32 + c];
    }
    if (tid < SROWS) {
        int r = tid;
        int grow = (r < 12) ? (j0 + r) : (r < 24) ? (H_ + j0 + r - 12) : (2 * H_ + j0 + r - 24);
        bi[r] = b_ih[grow]; bh[r] = b_hh[grow];
    }
    __syncthreads();

    for (int t = 0; t < T_; t++) {
        const float* hp = g_hseq + (size_t)t * BH_;
        float* ho = g_hseq + (size_t)(t + 1) * BH_;

        // ---- async stage: xs (inputs) + h chunk 0 -> stA ----
#pragma unroll
        for (int rr = 0; rr < 4; rr++) {
            int i = tid + 256 * rr;            // < 1024
            int b = i >> 3, part = i & 7;
            const float* src;
            float* dst;
            if (part < 4) {
                src = g_xin + ((size_t)(b0 + b) * T_ + t) * M_ + part * 4;
                dst = xs + b * XSP + part * 4;
            } else {
                src = Xc + ((size_t)(b0 + b) * T_ + t) * C_ + (part - 4) * 4;
                dst = xs + b * XSP + 16 + (part - 4) * 4;
            }
            CP_ASYNC16(dst, src);
        }
#pragma unroll
        for (int rr = 0; rr < 8; rr++) {
            int i = tid + 256 * rr;            // < 2048
            int b = i >> 4, k4 = i & 15;
            CP_ASYNC16(stA + b * STP + k4 * 4, hp + (size_t)(b0 + b) * H_ + k4 * 4);
        }
        CP_COMMIT();

        unsigned long long acc[RPW][4];
#pragma unroll
        for (int r = 0; r < RPW; r++)
#pragma unroll
            for (int b = 0; b < 4; b++) acc[r][b] = 0ull;

        for (int c = 0; c < 12; c++) {
            CP_WAIT0();
            __syncthreads();
            float* cur = (c & 1) ? stB : stA;
            float* nxt = (c & 1) ? stA : stB;
            if (c < 11) {
                const float* base = hp + (size_t)b0 * H_ + (c + 1) * 64;
#pragma unroll
                for (int rr = 0; rr < 8; rr++) {
                    int i = tid + 256 * rr;
                    int b = i >> 4, k4 = i & 15;
                    CP_ASYNC16(nxt + b * STP + k4 * 4, base + (size_t)b * H_ + k4 * 4);
                }
                CP_COMMIT();
            }
            const float* hb = cur + kgofs;
            const float* wb = Ws + c * 64 + kgofs;
#pragma unroll
            for (int k4 = 0; k4 < 32; k4 += 4) {
                ulonglong2 h4[4];
#pragma unroll
                for (int b = 0; b < 4; b++)
                    h4[b] = *(const ulonglong2*)(hb + (tx + 32 * b) * STP + k4);
#pragma unroll
                for (int r = 0; r < RPW; r++) {
                    ulonglong2 w4 = *(const ulonglong2*)(wb + (r0 + r) * 768 + k4);
#pragma unroll
                    for (int b = 0; b < 4; b++) {
                        FMA2(acc[r][b], w4.x, h4[b].x);
                        FMA2(acc[r][b], w4.y, h4[b].y);
                    }
                }
            }
        }
        __syncthreads();   // compute done; stA reusable

        // ---- phased reduction into gb = stA  [48][130] ----
        float* gb = stA;
        if (kg == 0) {     // P0: hidden partial + biases
#pragma unroll
            for (int r = 0; r < RPW; r++) {
                int gr = r0 + r;
#pragma unroll
                for (int b = 0; b < 4; b++) {
                    int bc = tx + 32 * b;
                    float s = usum_(acc[r][b]);
                    if (gr < 24) gb[gr * GBS + bc] = s + bh[gr] + bi[gr];
                    else {
                        gb[gr * GBS + bc] = s + bh[gr];
                        gb[(gr + 12) * GBS + bc] = bi[gr];
                    }
                }
            }
        }
        __syncthreads();
        if (kg == 1) {     // P1: add other hidden partial
#pragma unroll
            for (int r = 0; r < RPW; r++) {
                int gr = r0 + r;
#pragma unroll
                for (int b = 0; b < 4; b++)
                    gb[gr * GBS + tx + 32 * b] += usum_(acc[r][b]);
            }
        }
        __syncthreads();

        // ---- input part: 16 cols per k-group ----
        unsigned long long ax[RPW][4];
#pragma unroll
        for (int r = 0; r < RPW; r++)
#pragma unroll
            for (int b = 0; b < 4; b++) ax[r][b] = 0ull;
        {
            const float* xb = xs + kg * 16;
            const float* wib = Wi + kg * 16;
#pragma unroll
            for (int c4 = 0; c4 < 16; c4 += 4) {
                ulonglong2 x4[4];
#pragma unroll
                for (int b = 0; b < 4; b++)
                    x4[b] = *(const ulonglong2*)(xb + (tx + 32 * b) * XSP + c4);
#pragma unroll
                for (int r = 0; r < RPW; r++) {
                    ulonglong2 w4 = *(const ulonglong2*)(wib + (r0 + r) * 32 + c4);
#pragma unroll
                    for (int b = 0; b < 4; b++) {
                        FMA2(ax[r][b], w4.x, x4[b].x);
                        FMA2(ax[r][b], w4.y, x4[b].y);
                    }
                }
            }
        }
        if (kg == 0) {     // P2
#pragma unroll
            for (int r = 0; r < RPW; r++) {
                int gr = r0 + r;
                int tr = (gr < 24) ? gr : gr + 12;
#pragma unroll
                for (int b = 0; b < 4; b++)
                    gb[tr * GBS + tx + 32 * b] += usum_(ax[r][b]);
            }
        }
        __syncthreads();
        if (kg == 1) {     // P3
#pragma unroll
            for (int r = 0; r < RPW; r++) {
                int gr = r0 + r;
                int tr = (gr < 24) ? gr : gr + 12;
#pragma unroll
                for (int b = 0; b < 4; b++)
                    gb[tr * GBS + tx + 32 * b] += usum_(ax[r][b]);
            }
        }
        __syncthreads();

        // ---- gates + state update ----
        for (int e = tid; e < HSL * 128; e += GT_) {
            int j = e % 12, b = e / 12;
            float rg_ = sigmoidf_(gb[j * GBS + b]);
            float zg  = sigmoidf_(gb[(12 + j) * GBS + b]);
            float hn  = gb[(24 + j) * GBS + b];
            float inn = gb[(36 + j) * GBS + b];
            float n   = tanhf(inn + rg_ * hn);
            float hv  = hp[(size_t)(b0 + b) * H_ + j0 + j];
            ho[(size_t)(b0 + b) * H_ + j0 + j] = (1.f - zg) * n + zg * hv;
        }

        // ---- grid barrier ----
        if (t < T_ - 1) {
            __threadfence();
            __syncthreads();
            if (tid == 0) {
                unsigned tgt = (unsigned)t + 1u;
                if (atomicAdd(&g_arrive, 1u) == 127u) {
                    g_arrive = 0u;
                    __threadfence();
                    *(volatile unsigned*)&g_release = tgt;
                } else {
                    while (*(volatile unsigned*)&g_release < tgt) { __nanosleep(32); }
                }
                __threadfence();
            }
            __syncthreads();
        }
    }
}

// =====================================================================
// kernel 5: heads
// =====================================================================
__global__ void __launch_bounds__(256, 1)
heads_kernel(const float* __restrict__ Xc,
             const float* __restrict__ wraw_w, const float* __restrict__ wraw_b,
             const float* __restrict__ ctrl_w, const float* __restrict__ ctrl_b,
             const float* __restrict__ reg_emb, const float* __restrict__ bias,
             float* __restrict__ out_y, float* __restrict__ out_w, float* __restrict__ out_c) {
    extern __shared__ float hsm[];
    float* sww = hsm;
    float* scw = sww + 12288;
    float* scb = scw + 12288;
    float* srg = scb + 768;
    float* swb = srg + 768;
    int tid = threadIdx.x;
    for (int e = tid; e < 12288; e += 256) { sww[e] = wraw_w[e]; scw[e] = ctrl_w[e]; }
    for (int e = tid; e < 768; e += 256) { scb[e] = ctrl_b[e]; srg[e] = reg_emb[e]; }
    if (tid < 16) swb[tid] = wraw_b[tid];
    __syncthreads();

    int wid = tid >> 5, lane = tid & 31;
    float bias0 = bias[0];

    float rp = 0.f;
#pragma unroll
    for (int i = 0; i < 24; i++) rp += srg[lane + 32 * i];
    rp = wredux(rp) * 0.3f;

    for (int it = 0; it < 8; it++) {
        int n = blockIdx.x * 64 + wid * 8 + it;
        int b = n >> 9, t = n & 511;

        const float* hrow = g_hseq + (size_t)(t + 1) * BH_ + (size_t)b * H_;
        float hv[24];
#pragma unroll
        for (int i = 0; i < 24; i++) hv[i] = hrow[lane + 32 * i];
        float wp[16];
#pragma unroll
        for (int m = 0; m < 16; m++) {
            float p = 0.f;
#pragma unroll
            for (int i = 0; i < 24; i++) p += hv[i] * sww[m * 768 + lane + 32 * i];
            p = wredux(p);
            wp[m] = softplusf_(p + swb[m]);
        }
        if (t == 0) {
            const float* h2 = g_hseq + (size_t)2 * BH_ + (size_t)b * H_;
            float h2v[24];
#pragma unroll
            for (int i = 0; i < 24; i++) h2v[i] = h2[lane + 32 * i];
#pragma unroll
            for (int m = 0; m < 16; m++) {
                float p = 0.f;
#pragma unroll
                for (int i = 0; i < 24; i++) p += h2v[i] * sww[m * 768 + lane + 32 * i];
                p = wredux(p);
                wp[m] = 0.5f * softplusf_(p + swb[m]) + 0.5f * wp[m];
            }
        }

        float media = 0.f;
        const float* hillrow = g_hill + ((size_t)b * T_ + t) * M_;
        float cb[16];
#pragma unroll
        for (int m = 0; m < 16; m++) { cb[m] = hillrow[m] * wp[m]; media += cb[m]; }

        float xc[16];
#pragma unroll
        for (int c = 0; c < 16; c++) xc[c] = Xc[((size_t)b * T_ + t) * C_ + c];
        float ct = 0.f;
#pragma unroll
        for (int i = 0; i < 24; i++) {
            int j = lane + 32 * i;
            float s = scb[j];
#pragma unroll
            for (int c = 0; c < 16; c++) s += xc[c] * scw[j * 16 + c];
            ct += fmaxf(s, 0.f);
        }
        ct = wredux(ct) * 0.3f;

        float y = media + ct + rp + bias0;
        if (lane == 0) out_y[(size_t)b * T_ + t] = y;
        if (out_w && lane < 16) out_w[((size_t)b * T_ + t) * M_ + lane] = wp[lane];
        if (out_c && lane < 16) out_c[((size_t)b * T_ + t) * M_ + lane] = cb[lane];
    }
}

// =====================================================================
// launch
// =====================================================================
extern "C" void kernel_launch(void* const* d_in, const int* in_sizes, int n_in,
                              void* d_out, int out_size) {
    const float* Xm     = (const float*)d_in[0];
    const float* Xc     = (const float*)d_in[1];
    const float* A      = (const float*)d_in[3];
    const float* ew1    = (const float*)d_in[4];
    const float* eb1    = (const float*)d_in[5];
    const float* ew2    = (const float*)d_in[6];
    const float* eb2    = (const float*)d_in[7];
    const float* nw     = (const float*)d_in[8];
    const float* nb     = (const float*)d_in[9];
    const float* W_ih   = (const float*)d_in[10];
    const float* W_hh   = (const float*)d_in[11];
    const float* b_ih   = (const float*)d_in[12];
    const float* b_hh   = (const float*)d_in[13];
    const float* wraw_w = (const float*)d_in[14];
    const float* wraw_b = (const float*)d_in[15];
    const float* alpha  = (const float*)d_in[16];
    const float* hill_a = (const float*)d_in[17];
    const float* hill_g = (const float*)d_in[18];
    const float* ctrl_w = (const float*)d_in[19];
    const float* ctrl_b = (const float*)d_in[20];
    const float* regemb = (const float*)d_in[21];
    const float* bias   = (const float*)d_in[22];
    const float* h0     = (const float*)d_in[23];

    const int GRU_SMEM  = SM_FLOATS * 4;                                 // 203584
    const int HEAD_SMEM = (12288 + 12288 + 768 + 768 + 16) * 4;          // 104512
    cudaFuncSetAttribute(gru_persist_kernel, cudaFuncAttributeMaxDynamicSharedMemorySize, GRU_SMEM);
    cudaFuncSetAttribute(heads_kernel, cudaFuncAttributeMaxDynamicSharedMemorySize, HEAD_SMEM);

    enc_kernel<<<BT_ / 256, 256>>>(Xm, A, ew1, eb1, ew2, eb2, nw, nb);
    adstock_kernel<<<(B_ * M_) / 256, 256>>>(Xm, alpha, hill_a, hill_g);
    hinit_kernel<<<BH_ / 256, 256>>>(h0);

    gru_persist_kernel<<<128, GT_, GRU_SMEM>>>(Xc, W_ih, W_hh, b_ih, b_hh);

    float* out = (float*)d_out;
    float* oy = out;
    float* ow = nullptr;
    float* oc = nullptr;
    if (out_size >= BT_ + 2 * BTM_) { ow = out + BT_; oc = out + BT_ + BTM_; }
    else if (out_size >= BT_ + BTM_) { ow = out + BT_; }

    heads_kernel<<<BT_ / 64, 256, HEAD_SMEM>>>(Xc, wraw_w, wraw_b, ctrl_w, ctrl_b,
                                               regemb, bias, oy, ow, oc);
}